// round 17
// baseline (speedup 1.0000x reference)
#include <cuda_runtime.h>
#include <cuda_bf16.h>
#include <cstdint>
#include <cstddef>

#define N_NODES 50000
#define FEAT 128
#define WSTRIDE 136   // bf16 elements per row in smem (272B = 17 * 16B -> conflict-free ldmatrix)

// ---------------- scratch (static device globals; no allocs) ----------------
// NOTE: g_needed relies on the all-zero invariant: zero-initialized at module
// load, and gemm2 clears exactly the entries mark_zero set.
__device__ __align__(16) unsigned char g_needed[N_NODES];
__device__ int                         g_cnt[N_NODES];
__device__ __align__(16) float         g_accT[(size_t)N_NODES * FEAT];
__device__ __align__(16) float         g_T[(size_t)N_NODES * FEAT];
__device__ int                         g_is64;
__device__ __align__(16) unsigned short g_Whi[128 * WSTRIDE];        // W1^T hi, padded [n][k]
__device__ __align__(16) unsigned short g_Wlo[128 * WSTRIDE];        // W1^T lo, padded [n][k]
__device__ __align__(16) unsigned short g_W2hi[128 * WSTRIDE];       // W2^T hi
__device__ __align__(16) unsigned short g_W2lo[128 * WSTRIDE];       // W2^T lo

__device__ __forceinline__ uint32_t smem_u32(const void* p) {
    uint32_t a;
    asm("{ .reg .u64 t; cvta.to.shared.u64 t, %1; cvt.u32.u64 %0, t; }" : "=r"(a) : "l"(p));
    return a;
}

#define LDSM4(r, addr) \
    asm volatile("ldmatrix.sync.aligned.m8n8.x4.shared.b16 {%0,%1,%2,%3}, [%4];" \
        : "=r"((r)[0]), "=r"((r)[1]), "=r"((r)[2]), "=r"((r)[3]) : "r"(addr))

#define MMA16816(d, a, b0, b1) \
    asm volatile("mma.sync.aligned.m16n8k16.row.col.f32.bf16.bf16.f32 " \
        "{%0,%1,%2,%3}, {%4,%5,%6,%7}, {%8,%9}, {%0,%1,%2,%3};" \
        : "+f"((d)[0]), "+f"((d)[1]), "+f"((d)[2]), "+f"((d)[3]) \
        : "r"((a)[0]), "r"((a)[1]), "r"((a)[2]), "r"((a)[3]), "r"(b0), "r"(b1))

#define REDV4(ptr, v) \
    asm volatile("red.global.add.v4.f32 [%0], {%1,%2,%3,%4};" \
        :: "l"(ptr), "f"((v).x), "f"((v).y), "f"((v).z), "f"((v).w) : "memory")

// ---------------------------------------------------------------------------
// mark_zero: (a) detect index dtype per-CTA and publish g_is64;
// (b) W1+W2 split into bf16 hi/lo padded global images (first 128 CTAs);
// (c) mark needed nodes + zero their cnt and accT row (one warp per node_idx).
// ---------------------------------------------------------------------------
__global__ __launch_bounds__(256)
void mark_zero_kernel(const int* __restrict__ edges_raw,
                      const void* __restrict__ node_idx,
                      const float* __restrict__ W1,
                      const float* __restrict__ W2,
                      int B, int E2)
{
    __shared__ int s64;
    int tid = threadIdx.x;

    // --- per-CTA dtype detect: int64 arrays of idx<2^31 have zero odd words ---
    if (tid < 32) {
        int n = E2 < 2048 ? E2 : 2048;
        int any = 0;
        for (int i = 1 + 2 * tid; i < n; i += 64) any |= edges_raw[i];
        #pragma unroll
        for (int o = 16; o; o >>= 1) any |= __shfl_xor_sync(0xffffffffu, any, o);
        if (tid == 0) s64 = (any == 0) ? 1 : 0;
    }
    __syncthreads();
    int is64 = s64;
    if (blockIdx.x == 0 && tid == 0) g_is64 = is64;

    // --- W split (piggy-backed; 2*16384 elements over first 128 CTAs) ---
    {
        int widx = blockIdx.x * 256 + tid;
        if (widx < 32768) {
            const float* Wsrc = (widx < 16384) ? W1 : W2;
            int lidx = widx & 16383;
            int k = lidx >> 7, n = lidx & 127;       // coalesced read
            float w = Wsrc[lidx];
            __nv_bfloat16 hi = __float2bfloat16(w);
            __nv_bfloat16 lo = __float2bfloat16(w - __bfloat162float(hi));
            unsigned short hs, ls;
            *(__nv_bfloat16*)&hs = hi;
            *(__nv_bfloat16*)&ls = lo;
            if (widx < 16384) { g_Whi[n * WSTRIDE + k]  = hs; g_Wlo[n * WSTRIDE + k]  = ls; }
            else              { g_W2hi[n * WSTRIDE + k] = hs; g_W2lo[n * WSTRIDE + k] = ls; }
        }
    }

    // --- mark + zero (one warp per node) ---
    int w    = (blockIdx.x * 256 + tid) >> 5;
    int lane = tid & 31;
    if (w >= B) return;
    long long s = is64 ? ((const long long*)node_idx)[w]
                       : (long long)((const int*)node_idx)[w];
    if ((unsigned long long)s >= (unsigned long long)N_NODES) return;
    if (lane == 0) { g_needed[s] = 1; g_cnt[s] = 0; }
    *(float4*)&g_accT[(size_t)s * FEAT + lane * 4] = make_float4(0.f, 0.f, 0.f, 0.f);
}

// ---------------------------------------------------------------------------
// smem layout GEMM1 (64-row x 128-col tiles, 2 CTAs/SM).
// ---------------------------------------------------------------------------
#define SM_XHI  0
#define SM_XLO  (SM_XHI + 64 * WSTRIDE * 2)
#define SM_WHI  (SM_XLO + 64 * WSTRIDE * 2)
#define SM_WLO  (SM_WHI + 128 * WSTRIDE * 2)
#define SM_TOT  (SM_WLO + 128 * WSTRIDE * 2)

// smem layout GEMM2 (32-row x 64-col tiles, 4 CTAs/SM).
#define SM2_XHI  0
#define SM2_XLO  (SM2_XHI + 32 * WSTRIDE * 2)
#define SM2_WHI  (SM2_XLO + 32 * WSTRIDE * 2)
#define SM2_WLO  (SM2_WHI + 64 * WSTRIDE * 2)
#define SM2_FLAG (SM2_WLO + 64 * WSTRIDE * 2)
#define SM2_TOT  (SM2_FLAG + 128)

// Convert 8 contiguous floats -> hi/lo bf16x2 quads and store to smem row.
__device__ __forceinline__ void split_store(char* smem, int xhi, int xlo,
                                            int r, int c0, float4 v0, float4 v1)
{
    float xs[8] = {v0.x, v0.y, v0.z, v0.w, v1.x, v1.y, v1.z, v1.w};
    unsigned hi[4], lo[4];
    #pragma unroll
    for (int p = 0; p < 4; p++) {
        float a = xs[2 * p], b = xs[2 * p + 1];
        __nv_bfloat162 h = __floats2bfloat162_rn(a, b);
        float2 hf = __bfloat1622float2(h);
        __nv_bfloat162 l = __floats2bfloat162_rn(a - hf.x, b - hf.y);
        hi[p] = *(unsigned*)&h;
        lo[p] = *(unsigned*)&l;
    }
    int off = (r * WSTRIDE + c0) * 2;
    *(uint4*)(smem + xhi + off) = make_uint4(hi[0], hi[1], hi[2], hi[3]);
    *(uint4*)(smem + xlo + off) = make_uint4(lo[0], lo[1], lo[2], lo[3]);
}

// ---------------------------------------------------------------------------
// GEMM1 via mma.sync (HMMA bf16, 3-pass split): T = tanh(X @ W1 + b1).
// ---------------------------------------------------------------------------
__global__ __launch_bounds__(256, 2)
void gemm1_mma_kernel(const float* __restrict__ X,
                      const float* __restrict__ b1,
                      int Nrows)
{
    extern __shared__ char smem[];
    uint32_t sb  = smem_u32(smem);
    int tid  = threadIdx.x;
    int wid  = tid >> 5;
    int lane = tid & 31;
    int row0 = blockIdx.x * 64;

    for (int i = tid * 16; i < 128 * WSTRIDE * 2; i += 256 * 16) {
        *(uint4*)(smem + SM_WHI + i) = *(const uint4*)((const char*)g_Whi + i);
        *(uint4*)(smem + SM_WLO + i) = *(const uint4*)((const char*)g_Wlo + i);
    }

    {
        int r  = tid & 63;
        int q  = tid >> 6;
        int gr = row0 + r;
        const float* xr = X + (size_t)gr * FEAT;
        #pragma unroll
        for (int j = 0; j < 4; j++) {
            int c0 = q * 32 + j * 8;
            float4 v0 = make_float4(0.f, 0.f, 0.f, 0.f), v1 = v0;
            if (gr < Nrows) {
                v0 = *(const float4*)&xr[c0];
                v1 = *(const float4*)&xr[c0 + 4];
            }
            split_store(smem, SM_XHI, SM_XLO, r, c0, v0, v1);
        }
    }
    __syncthreads();

    // fragment bases
    int sub = lane >> 3, rr = lane & 7;
    int wr = (wid & 3) * 16;
    int wc = (wid >> 2) * 64;
    uint32_t aOff = (uint32_t)(((wr + (sub & 1) * 8 + rr) * WSTRIDE + (sub >> 1) * 8) * 2);
    uint32_t bOff = (uint32_t)(((wc + (sub >> 1) * 8 + rr) * WSTRIDE + (sub & 1) * 8) * 2);

    float d[8][4];
    #pragma unroll
    for (int j = 0; j < 8; j++)
        #pragma unroll
        for (int q = 0; q < 4; q++) d[j][q] = 0.f;

    #pragma unroll 1
    for (int pass = 0; pass < 3; pass++) {
        uint32_t aBase = sb + ((pass < 2)  ? SM_XHI : SM_XLO) + aOff;
        uint32_t bBase = sb + ((pass == 1) ? SM_WLO : SM_WHI) + bOff;
        #pragma unroll 4
        for (int ks = 0; ks < 8; ks++) {
            uint32_t a[4];
            LDSM4(a, aBase + (uint32_t)ks * 32);
            uint32_t bAddr = bBase + (uint32_t)ks * 32;
            #pragma unroll
            for (int np = 0; np < 4; np++) {
                uint32_t b[4];
                LDSM4(b, bAddr + (uint32_t)(np * 16 * WSTRIDE * 2));
                MMA16816(d[np * 2],     a, b[0], b[1]);
                MMA16816(d[np * 2 + 1], a, b[2], b[3]);
            }
        }
    }

    {
        int g = lane >> 2, c = lane & 3;
        int gr0 = row0 + wr + g, gr1 = gr0 + 8;
        #pragma unroll
        for (int j = 0; j < 8; j++) {
            int col = wc + j * 8 + c * 2;
            float bx = b1[col], by = b1[col + 1];
            if (gr0 < Nrows) {
                float2 o;
                o.x = tanhf(d[j][0] + bx);
                o.y = tanhf(d[j][1] + by);
                *(float2*)&g_T[(size_t)gr0 * FEAT + col] = o;
            }
            if (gr1 < Nrows) {
                float2 o;
                o.x = tanhf(d[j][2] + bx);
                o.y = tanhf(d[j][3] + by);
                *(float2*)&g_T[(size_t)gr1 * FEAT + col] = o;
            }
        }
    }
}

// ---------------------------------------------------------------------------
// Fused edge filter + aggregation: single pass over edges (R14-verified).
// ---------------------------------------------------------------------------
__global__ __launch_bounds__(256)
void edge_kernel(const void* __restrict__ edges,
                 const int* __restrict__ ind_ptr,
                 int E)
{
    int gtid = blockIdx.x * blockDim.x + threadIdx.x;
    int lane = threadIdx.x & 31;
    int e    = gtid;
    int is64 = g_is64;
    int keep_self = (*ind_ptr < 2);
    int co = lane * 4;

    int src = 0, dst = 0;
    bool act = false;
    if (e < E) {
        if (is64) { longlong2 p = ((const longlong2*)edges)[e]; src = (int)p.x; dst = (int)p.y; }
        else      { int2 p = ((const int2*)edges)[e];           src = p.x;      dst = p.y; }
        act = ((src != dst) | keep_self)
              && ((unsigned)src < (unsigned)N_NODES)
              && ((unsigned)dst < (unsigned)N_NODES)
              && g_needed[src];
    }
    unsigned m = __ballot_sync(0xffffffffu, act);
    if (act) atomicAdd(&g_cnt[src], 1);
    while (m) {
        int l = __ffs(m) - 1;
        m &= m - 1;
        int s = __shfl_sync(0xffffffffu, src, l);
        int d = __shfl_sync(0xffffffffu, dst, l);
        float4 hv = *(const float4*)&g_T[(size_t)d * FEAT + co];
        REDV4(&g_accT[(size_t)s * FEAT + co], hv);
    }
}

// ---------------------------------------------------------------------------
// GEMM2 via mma.sync, 32-row x 64-col tiles (grid = 2*ceil(B/32), 4 CTAs/SM):
// out[i] = flag_i * ((accT[s_i]/cnt_i) @ W2 + b2); clears g_needed[s_i].
// blockIdx: row_tile = bid>>1, col_half = bid&1.
// Warp w: rows (w&1)*16..+15, cols (w>>1)*16..+15 (within the 64-col half).
// ---------------------------------------------------------------------------
__global__ __launch_bounds__(256, 4)
void gemm2_mma_kernel(const void* __restrict__ node_idx,
                      const float* __restrict__ b2,
                      float* __restrict__ out,
                      int B)
{
    extern __shared__ char smem[];
    uint32_t sb  = smem_u32(smem);
    float* sFlag = (float*)(smem + SM2_FLAG);
    int tid  = threadIdx.x;
    int wid  = tid >> 5;
    int lane = tid & 31;
    int i0   = (blockIdx.x >> 1) * 32;
    int colh = (blockIdx.x & 1) * 64;
    int is64 = g_is64;

    // --- copy this half's W2 image rows [colh, colh+64) (17408B each) ---
    {
        const char* srcHi = (const char*)g_W2hi + colh * WSTRIDE * 2;
        const char* srcLo = (const char*)g_W2lo + colh * WSTRIDE * 2;
        for (int i = tid * 16; i < 64 * WSTRIDE * 2; i += 256 * 16) {
            *(uint4*)(smem + SM2_WHI + i) = *(const uint4*)(srcHi + i);
            *(uint4*)(smem + SM2_WLO + i) = *(const uint4*)(srcLo + i);
        }
    }

    // --- gather + scale + split A = accT[node_idx[i]] / cnt (full K=128) ---
    {
        int r = tid & 31;             // row 0..31 (8 threads per row)
        int q = tid >> 5;             // 0..7, 16-col slice
        int i = i0 + r;
        float  scale = 0.f;
        size_t s = 0;
        int    c = 0;
        bool   valid = (i < B);
        if (valid) {
            long long sv = is64 ? ((const long long*)node_idx)[i]
                                : (long long)((const int*)node_idx)[i];
            if ((unsigned long long)sv < (unsigned long long)N_NODES) {
                s = (size_t)sv;
                c = g_cnt[s];
            } else valid = false;
            scale = (c > 0) ? (1.f / (float)c) : 0.f;
        }
        if (q == 0) {
            sFlag[r] = (valid && c > 0) ? 1.f : 0.f;
            if (valid) g_needed[s] = 0;   // restore all-zero invariant
        }
        const float* ar = &g_accT[s * FEAT];
        #pragma unroll
        for (int j = 0; j < 2; j++) {
            int c0 = q * 16 + j * 8;
            float4 v0 = make_float4(0.f, 0.f, 0.f, 0.f), v1 = v0;
            if (valid) {
                v0 = *(const float4*)&ar[c0];
                v1 = *(const float4*)&ar[c0 + 4];
                v0.x *= scale; v0.y *= scale; v0.z *= scale; v0.w *= scale;
                v1.x *= scale; v1.y *= scale; v1.z *= scale; v1.w *= scale;
            }
            split_store(smem, SM2_XHI, SM2_XLO, r, c0, v0, v1);
        }
    }
    __syncthreads();

    // --- fragment bases: warp = rows (wid&1)*16, local cols (wid>>1)*16 ---
    int sub = lane >> 3, rr = lane & 7;
    int wr = (wid & 1) * 16;
    int wc = (wid >> 1) * 16;
    uint32_t aOff = (uint32_t)(((wr + (sub & 1) * 8 + rr) * WSTRIDE + (sub >> 1) * 8) * 2);
    uint32_t bOff = (uint32_t)(((wc + (sub >> 1) * 8 + rr) * WSTRIDE + (sub & 1) * 8) * 2);

    float d[2][4];
    #pragma unroll
    for (int j = 0; j < 2; j++)
        #pragma unroll
        for (int q = 0; q < 4; q++) d[j][q] = 0.f;

    #pragma unroll 1
    for (int pass = 0; pass < 3; pass++) {
        uint32_t aBase = sb + ((pass < 2)  ? SM2_XHI : SM2_XLO) + aOff;
        uint32_t bBase = sb + ((pass == 1) ? SM2_WLO : SM2_WHI) + bOff;
        #pragma unroll 4
        for (int ks = 0; ks < 8; ks++) {
            uint32_t a[4], b[4];
            LDSM4(a, aBase + (uint32_t)ks * 32);
            LDSM4(b, bBase + (uint32_t)ks * 32);
            MMA16816(d[0], a, b[0], b[1]);
            MMA16816(d[1], a, b[2], b[3]);
        }
    }

    // --- epilogue: flag * (d + b2) ---
    {
        int g = lane >> 2, c = lane & 3;
        int r0 = wr + g, r1 = r0 + 8;
        int ir0 = i0 + r0, ir1 = i0 + r1;
        float f0 = sFlag[r0], f1 = sFlag[r1];
        #pragma unroll
        for (int j = 0; j < 2; j++) {
            int col = colh + wc + j * 8 + c * 2;
            float bx = b2[col], by = b2[col + 1];
            if (ir0 < B) {
                float2 o;
                o.x = f0 * (d[j][0] + bx);
                o.y = f0 * (d[j][1] + by);
                *(float2*)&out[(size_t)ir0 * FEAT + col] = o;
            }
            if (ir1 < B) {
                float2 o;
                o.x = f1 * (d[j][2] + bx);
                o.y = f1 * (d[j][3] + by);
                *(float2*)&out[(size_t)ir1 * FEAT + col] = o;
            }
        }
    }
}

// ---------------------------------------------------------------------------
extern "C" void kernel_launch(void* const* d_in, const int* in_sizes, int n_in,
                              void* d_out, int out_size)
{
    const void*  edges    = d_in[0];
    const void*  node_idx = d_in[1];
    const float* X        = (const float*)d_in[2];
    const float* W1       = (const float*)d_in[3];
    const float* b1       = (const float*)d_in[4];
    const float* W2       = (const float*)d_in[5];
    const float* b2       = (const float*)d_in[6];
    const int*   ind      = (const int*)d_in[7];

    int E = in_sizes[0] / 2;
    int B = in_sizes[1];
    int N = in_sizes[2] / FEAT;
    float* out = (float*)d_out;

    cudaFuncSetAttribute(gemm1_mma_kernel, cudaFuncAttributeMaxDynamicSharedMemorySize, SM_TOT);
    cudaFuncSetAttribute(gemm2_mma_kernel, cudaFuncAttributeMaxDynamicSharedMemorySize, SM2_TOT);

    mark_zero_kernel<<<(B * 32 + 255) / 256, 256>>>((const int*)edges, node_idx, W1, W2, B, in_sizes[0]);
    gemm1_mma_kernel<<<(N + 63) / 64, 256, SM_TOT>>>(X, b1, N);
    edge_kernel<<<(E + 255) / 256, 256>>>(edges, ind, E);
    gemm2_mma_kernel<<<2 * ((B + 31) / 32), 256, SM2_TOT>>>(node_idx, b2, out, B);
}